// round 7
// baseline (speedup 1.0000x reference)
#include <cuda_runtime.h>
#include <cuda_bf16.h>
#include <math.h>
#include <stdint.h>

// Problem shapes (fixed by the reference)
#define BATCH 16
#define KQ    512
#define NK    2048
#define DIM   1024

// ---------------- scratch (no cudaMalloc allowed) ----------------
__device__ float g_qW[KQ * DIM];                    // 2 MB
__device__ float g_qW_part[8 * KQ * DIM];           // 16 MB split-K partials
__device__ float g_att_scratch[BATCH * KQ * NK];    // 64 MB (if att not in d_out)
__device__ int   g_mask_kind;                       // 0=int32, 1=uint8, 2=float32

// ---------------- helpers ----------------
__device__ __forceinline__ float rna_tf32(float x) {
    float y;
    asm("cvt.rna.tf32.f32 %0, %1;" : "=f"(y) : "f"(x));
    return y;
}
__device__ __forceinline__ float4 rna4(float4 v) {
    v.x = rna_tf32(v.x); v.y = rna_tf32(v.y);
    v.z = rna_tf32(v.z); v.w = rna_tf32(v.w);
    return v;
}
__device__ __forceinline__ void mma_tf32(float* c, const uint32_t* a, const uint32_t* b) {
    asm volatile(
        "mma.sync.aligned.m16n8k8.row.col.f32.tf32.tf32.f32 "
        "{%0,%1,%2,%3}, {%4,%5,%6,%7}, {%8,%9}, {%0,%1,%2,%3};"
        : "+f"(c[0]), "+f"(c[1]), "+f"(c[2]), "+f"(c[3])
        : "r"(a[0]), "r"(a[1]), "r"(a[2]), "r"(a[3]), "r"(b[0]), "r"(b[1]));
}

// Pair-swizzle: tile row r holds 8 float2 slots; logical slot s (= g*4 + tig,
// containing k-cols {8g+tig, 8g+tig+4}) lives at physical slot s ^ m(r),
// m(r) = r2 | ((r0^r3)<<1) | (r1<<2).  Conflict-free for paired LDS.64
// fragment loads (per 16-lane phase) and paired STS.64 stores.
__device__ __forceinline__ int swz(int r, int s) {
    int m = ((r >> 2) & 1) | (((r ^ (r >> 3)) & 1) << 1) | (((r >> 1) & 1) << 2);
    return s ^ m;
}

#define SBS 136    // NN B tile: 128 n-cols + 8 pad

// =====================================================================
// tf32 mma.sync GEMM, NT: C[M,N] = alpha * A[M,Kd] * B[N,Kd]^T
// Block 128x128, 4 warps (2x2), warp tile 64x64, K-chunk 16,
// 2-stage double buffer, pair-swizzled tiles (LDS.64 fragments).
// =====================================================================
__global__ void __launch_bounds__(128) gemm_nt_mma(
    const float* __restrict__ A, const float* __restrict__ B, float* __restrict__ C,
    int Kd, int lda, int ldb, int ldc, long sA, long sB, long sC, float alpha)
{
    __shared__ float As[2][128 * 16];
    __shared__ float Bs[2][128 * 16];

    const int tid  = threadIdx.x;
    const int wid  = tid >> 5;
    const int lane = tid & 31;
    const int wm   = wid & 1;
    const int wn   = wid >> 1;
    const int grp  = lane >> 2;
    const int tig  = lane & 3;
    const int lrow = (wid << 4) + (lane & 15);   // 0..63 (+64 on pass 2)
    const int lh   = (lane >> 4) & 1;            // 8-col group

    A += (long)blockIdx.z * sA + (long)blockIdx.y * 128 * lda;
    B += (long)blockIdx.z * sB + (long)blockIdx.x * 128 * ldb;
    C += (long)blockIdx.z * sC + (long)blockIdx.y * 128 * ldc + (long)blockIdx.x * 128;

    float acc[4][8][4];
    #pragma unroll
    for (int i = 0; i < 4; i++)
        #pragma unroll
        for (int j = 0; j < 8; j++)
            #pragma unroll
            for (int t = 0; t < 4; t++) acc[i][j][t] = 0.f;

    const int NCH = Kd >> 4;
    float4 pa0[2], pa1[2], pb0[2], pb1[2];

    // ---- prologue: load + store chunk 0 ----
    #pragma unroll
    for (int i = 0; i < 2; i++) {
        int r = lrow + 64 * i;
        pa0[i] = *(const float4*)(A + (long)r * lda + 8 * lh);
        pa1[i] = *(const float4*)(A + (long)r * lda + 8 * lh + 4);
        pb0[i] = *(const float4*)(B + (long)r * ldb + 8 * lh);
        pb1[i] = *(const float4*)(B + (long)r * ldb + 8 * lh + 4);
    }
    #pragma unroll
    for (int i = 0; i < 2; i++) {
        int r = lrow + 64 * i;
        float a0[4], a1[4], b0[4], b1[4];
        *(float4*)a0 = rna4(pa0[i]); *(float4*)a1 = rna4(pa1[i]);
        *(float4*)b0 = rna4(pb0[i]); *(float4*)b1 = rna4(pb1[i]);
        #pragma unroll
        for (int j = 0; j < 4; j++) {
            int p = swz(r, lh * 4 + j);
            *(float2*)&As[0][r * 16 + 2 * p] = make_float2(a0[j], a1[j]);
            *(float2*)&Bs[0][r * 16 + 2 * p] = make_float2(b0[j], b1[j]);
        }
    }
    __syncthreads();

    for (int kc = 0; kc < NCH; kc++) {
        const int st = kc & 1;
        if (kc + 1 < NCH) {
            const float* An = A + (long)(kc + 1) * 16;
            const float* Bn = B + (long)(kc + 1) * 16;
            #pragma unroll
            for (int i = 0; i < 2; i++) {
                int r = lrow + 64 * i;
                pa0[i] = *(const float4*)(An + (long)r * lda + 8 * lh);
                pa1[i] = *(const float4*)(An + (long)r * lda + 8 * lh + 4);
                pb0[i] = *(const float4*)(Bn + (long)r * ldb + 8 * lh);
                pb1[i] = *(const float4*)(Bn + (long)r * ldb + 8 * lh + 4);
            }
        }

        #pragma unroll
        for (int g = 0; g < 2; g++) {
            uint32_t afr[4][4], bfr[8][2];
            #pragma unroll
            for (int mt = 0; mt < 4; mt++) {
                int r0 = wm * 64 + mt * 16 + grp;
                float2 x0 = *(const float2*)&As[st][r0 * 16 + 2 * swz(r0, g * 4 + tig)];
                float2 x1 = *(const float2*)&As[st][(r0 + 8) * 16 + 2 * swz(r0 + 8, g * 4 + tig)];
                afr[mt][0] = __float_as_uint(x0.x); afr[mt][2] = __float_as_uint(x0.y);
                afr[mt][1] = __float_as_uint(x1.x); afr[mt][3] = __float_as_uint(x1.y);
            }
            #pragma unroll
            for (int nt = 0; nt < 8; nt++) {
                int n0 = wn * 64 + nt * 8 + grp;
                float2 y = *(const float2*)&Bs[st][n0 * 16 + 2 * swz(n0, g * 4 + tig)];
                bfr[nt][0] = __float_as_uint(y.x); bfr[nt][1] = __float_as_uint(y.y);
            }
            #pragma unroll
            for (int mt = 0; mt < 4; mt++)
                #pragma unroll
                for (int nt = 0; nt < 8; nt++)
                    mma_tf32(acc[mt][nt], afr[mt], bfr[nt]);
        }

        if (kc + 1 < NCH) {
            const int sn = st ^ 1;
            #pragma unroll
            for (int i = 0; i < 2; i++) {
                int r = lrow + 64 * i;
                float a0[4], a1[4], b0[4], b1[4];
                *(float4*)a0 = rna4(pa0[i]); *(float4*)a1 = rna4(pa1[i]);
                *(float4*)b0 = rna4(pb0[i]); *(float4*)b1 = rna4(pb1[i]);
                #pragma unroll
                for (int j = 0; j < 4; j++) {
                    int p = swz(r, lh * 4 + j);
                    *(float2*)&As[sn][r * 16 + 2 * p] = make_float2(a0[j], a1[j]);
                    *(float2*)&Bs[sn][r * 16 + 2 * p] = make_float2(b0[j], b1[j]);
                }
            }
        }
        __syncthreads();
    }

    #pragma unroll
    for (int mt = 0; mt < 4; mt++) {
        int r0 = wm * 64 + mt * 16 + grp;
        #pragma unroll
        for (int nt = 0; nt < 8; nt++) {
            int c0 = wn * 64 + nt * 8 + 2 * tig;
            float2 v0 = make_float2(acc[mt][nt][0] * alpha, acc[mt][nt][1] * alpha);
            float2 v1 = make_float2(acc[mt][nt][2] * alpha, acc[mt][nt][3] * alpha);
            *(float2*)(C + (long)r0 * ldc + c0)       = v0;
            *(float2*)(C + (long)(r0 + 8) * ldc + c0) = v1;
        }
    }
}

// =====================================================================
// tf32 mma.sync GEMM, NN: C[M,N] = alpha * A[M,Kd] * B[Kd,N]
// A tile pair-swizzled (LDS.64); B tile [16 k][128 n] scalar (conflict-free).
// =====================================================================
__global__ void __launch_bounds__(128) gemm_nn_mma(
    const float* __restrict__ A, const float* __restrict__ B, float* __restrict__ C,
    int Kd, int lda, int ldb, int ldc, long sA, long sB, long sC, float alpha)
{
    __shared__ float As[2][128 * 16];
    __shared__ float Bs[2][16][SBS];

    const int tid  = threadIdx.x;
    const int wid  = tid >> 5;
    const int lane = tid & 31;
    const int wm   = wid & 1;
    const int wn   = wid >> 1;
    const int grp  = lane >> 2;
    const int tig  = lane & 3;
    const int lrow = (wid << 4) + (lane & 15);
    const int lh   = (lane >> 4) & 1;
    const int brow = tid >> 5;          // 0..3 (+4*i)
    const int bcol = (tid & 31) * 4;    // 0..124

    A += (long)blockIdx.z * sA + (long)blockIdx.y * 128 * lda;
    B += (long)blockIdx.z * sB + (long)blockIdx.x * 128;
    C += (long)blockIdx.z * sC + (long)blockIdx.y * 128 * ldc + (long)blockIdx.x * 128;

    float acc[4][8][4];
    #pragma unroll
    for (int i = 0; i < 4; i++)
        #pragma unroll
        for (int j = 0; j < 8; j++)
            #pragma unroll
            for (int t = 0; t < 4; t++) acc[i][j][t] = 0.f;

    const int NCH = Kd >> 4;
    float4 pa0[2], pa1[2], pb[4];

    #pragma unroll
    for (int i = 0; i < 2; i++) {
        int r = lrow + 64 * i;
        pa0[i] = *(const float4*)(A + (long)r * lda + 8 * lh);
        pa1[i] = *(const float4*)(A + (long)r * lda + 8 * lh + 4);
    }
    #pragma unroll
    for (int i = 0; i < 4; i++)
        pb[i] = *(const float4*)(B + (long)(brow + 4 * i) * ldb + bcol);

    #pragma unroll
    for (int i = 0; i < 2; i++) {
        int r = lrow + 64 * i;
        float a0[4], a1[4];
        *(float4*)a0 = rna4(pa0[i]); *(float4*)a1 = rna4(pa1[i]);
        #pragma unroll
        for (int j = 0; j < 4; j++) {
            int p = swz(r, lh * 4 + j);
            *(float2*)&As[0][r * 16 + 2 * p] = make_float2(a0[j], a1[j]);
        }
    }
    #pragma unroll
    for (int i = 0; i < 4; i++)
        *(float4*)&Bs[0][brow + 4 * i][bcol] = rna4(pb[i]);
    __syncthreads();

    for (int kc = 0; kc < NCH; kc++) {
        const int st = kc & 1;
        if (kc + 1 < NCH) {
            const float* An = A + (long)(kc + 1) * 16;
            const float* Bn = B + (long)(kc + 1) * 16 * ldb;
            #pragma unroll
            for (int i = 0; i < 2; i++) {
                int r = lrow + 64 * i;
                pa0[i] = *(const float4*)(An + (long)r * lda + 8 * lh);
                pa1[i] = *(const float4*)(An + (long)r * lda + 8 * lh + 4);
            }
            #pragma unroll
            for (int i = 0; i < 4; i++)
                pb[i] = *(const float4*)(Bn + (long)(brow + 4 * i) * ldb + bcol);
        }

        #pragma unroll
        for (int g = 0; g < 2; g++) {
            const int k0 = g * 8;
            uint32_t afr[4][4], bfr[8][2];
            #pragma unroll
            for (int mt = 0; mt < 4; mt++) {
                int r0 = wm * 64 + mt * 16 + grp;
                float2 x0 = *(const float2*)&As[st][r0 * 16 + 2 * swz(r0, g * 4 + tig)];
                float2 x1 = *(const float2*)&As[st][(r0 + 8) * 16 + 2 * swz(r0 + 8, g * 4 + tig)];
                afr[mt][0] = __float_as_uint(x0.x); afr[mt][2] = __float_as_uint(x0.y);
                afr[mt][1] = __float_as_uint(x1.x); afr[mt][3] = __float_as_uint(x1.y);
            }
            #pragma unroll
            for (int nt = 0; nt < 8; nt++) {
                int n0 = wn * 64 + nt * 8 + grp;
                bfr[nt][0] = __float_as_uint(Bs[st][k0 + tig][n0]);
                bfr[nt][1] = __float_as_uint(Bs[st][k0 + tig + 4][n0]);
            }
            #pragma unroll
            for (int mt = 0; mt < 4; mt++)
                #pragma unroll
                for (int nt = 0; nt < 8; nt++)
                    mma_tf32(acc[mt][nt], afr[mt], bfr[nt]);
        }

        if (kc + 1 < NCH) {
            const int sn = st ^ 1;
            #pragma unroll
            for (int i = 0; i < 2; i++) {
                int r = lrow + 64 * i;
                float a0[4], a1[4];
                *(float4*)a0 = rna4(pa0[i]); *(float4*)a1 = rna4(pa1[i]);
                #pragma unroll
                for (int j = 0; j < 4; j++) {
                    int p = swz(r, lh * 4 + j);
                    *(float2*)&As[sn][r * 16 + 2 * p] = make_float2(a0[j], a1[j]);
                }
            }
            #pragma unroll
            for (int i = 0; i < 4; i++)
                *(float4*)&Bs[sn][brow + 4 * i][bcol] = rna4(pb[i]);
        }
        __syncthreads();
    }

    #pragma unroll
    for (int mt = 0; mt < 4; mt++) {
        int r0 = wm * 64 + mt * 16 + grp;
        #pragma unroll
        for (int nt = 0; nt < 8; nt++) {
            int c0 = wn * 64 + nt * 8 + 2 * tig;
            float2 v0 = make_float2(acc[mt][nt][0] * alpha, acc[mt][nt][1] * alpha);
            float2 v1 = make_float2(acc[mt][nt][2] * alpha, acc[mt][nt][3] * alpha);
            *(float2*)(C + (long)r0 * ldc + c0)       = v0;
            *(float2*)(C + (long)(r0 + 8) * ldc + c0) = v1;
        }
    }
}

// ---------------- split-K reduction for qW ----------------
__global__ void __launch_bounds__(256) reduce_qw(
    const float* __restrict__ part, float* __restrict__ qW)
{
    int i = (blockIdx.x * 256 + threadIdx.x) * 4;
    float4 s = make_float4(0.f, 0.f, 0.f, 0.f);
    #pragma unroll
    for (int z = 0; z < 8; z++) {
        float4 v = *(const float4*)(part + (long)z * (KQ * DIM) + i);
        s.x += v.x; s.y += v.y; s.z += v.z; s.w += v.w;
    }
    const float a = 1.0f / 32.0f;
    s.x *= a; s.y *= a; s.z *= a; s.w *= a;
    *(float4*)(qW + i) = s;
}

// ---------------- mask dtype detection ----------------
__global__ void detect_mask_kind(const unsigned char* __restrict__ m)
{
    if (threadIdx.x != 0 || blockIdx.x != 0) return;
    int cnt[4] = {0, 0, 0, 0};
    for (int i = 0; i < 4096; i++)
        if (m[i] != 0) cnt[i & 3]++;
    int kind;
    if (cnt[1] > 0)                    kind = 1;  // uint8 bool
    else if (cnt[2] > 0 || cnt[3] > 0) kind = 2;  // float32
    else                               kind = 0;  // int32 bool
    g_mask_kind = kind;
}

// ---------------- fused mask + softmax ----------------
__global__ void __launch_bounds__(256) mask_softmax(
    float* __restrict__ att, const void* __restrict__ mask_raw)
{
    long row = blockIdx.x;
    float* p = att + row * (long)NK;
    int tid = threadIdx.x;
    int kind = g_mask_kind;

    const unsigned char* m8  = (const unsigned char*)mask_raw + row * (long)NK;
    const int*           m32 = (const int*)mask_raw           + row * (long)NK;
    const float*         mf  = (const float*)mask_raw         + row * (long)NK;

    float v[8];
    float lmax = -INFINITY;
    #pragma unroll
    for (int i = 0; i < 8; i++) {
        int idx = tid + i * 256;
        bool keep;
        if (kind == 0)      keep = (m32[idx] != 0);
        else if (kind == 1) keep = (m8[idx] != 0);
        else                keep = (mf[idx] != 0.0f);
        float s = keep ? p[idx] : -INFINITY;
        v[i] = s;
        lmax = fmaxf(lmax, s);
    }

    __shared__ float red[8];
    #pragma unroll
    for (int o = 16; o > 0; o >>= 1)
        lmax = fmaxf(lmax, __shfl_xor_sync(0xffffffffu, lmax, o));
    if ((tid & 31) == 0) red[tid >> 5] = lmax;
    __syncthreads();
    float rmax = fmaxf(fmaxf(fmaxf(red[0], red[1]), fmaxf(red[2], red[3])),
                       fmaxf(fmaxf(red[4], red[5]), fmaxf(red[6], red[7])));
    __syncthreads();

    float lsum = 0.f;
    #pragma unroll
    for (int i = 0; i < 8; i++) {
        float e = (v[i] == -INFINITY) ? 0.f : __expf(v[i] - rmax);
        v[i] = e;
        lsum += e;
    }
    #pragma unroll
    for (int o = 16; o > 0; o >>= 1)
        lsum += __shfl_xor_sync(0xffffffffu, lsum, o);
    if ((tid & 31) == 0) red[tid >> 5] = lsum;
    __syncthreads();
    float rsum = red[0] + red[1] + red[2] + red[3] + red[4] + red[5] + red[6] + red[7];
    float inv = (rsum > 0.f) ? (1.f / rsum) : 0.f;

    #pragma unroll
    for (int i = 0; i < 8; i++) p[tid + i * 256] = v[i] * inv;
}

// ---------------- launcher ----------------
extern "C" void kernel_launch(void* const* d_in, const int* in_sizes, int n_in,
                              void* d_out, int out_size)
{
    const float* query = (const float*)d_in[0];   // [KQ, DIM]
    const float* key   = (const float*)d_in[1];   // [BATCH, NK, DIM]
    const float* W     = (const float*)d_in[2];   // [DIM, DIM]
    const void*  mask  = d_in[3];                 // [BATCH, KQ, NK] bool

    float* out_ptr = (float*)d_out;
    const long outBKD = (long)BATCH * KQ * DIM;

    float *qW, *qW_part;
    cudaGetSymbolAddress((void**)&qW, g_qW);
    cudaGetSymbolAddress((void**)&qW_part, g_qW_part);
    float* att_ptr;
    if ((long)out_size > outBKD) {
        att_ptr = out_ptr + outBKD;
    } else {
        cudaGetSymbolAddress((void**)&att_ptr, g_att_scratch);
    }

    // 0) mask dtype detection
    detect_mask_kind<<<1, 1>>>((const unsigned char*)mask);

    // 1) qW partials via split-K=8 (256 CTAs), then deterministic reduce (/32)
    gemm_nn_mma<<<dim3(DIM / 128, KQ / 128, 8), 128>>>(
        query, W, qW_part, 128, DIM, DIM, DIM,
        128L, 128L * DIM, (long)KQ * DIM, 1.0f);
    reduce_qw<<<KQ * DIM / (256 * 4), 256>>>(qW_part, qW);

    // 2) att_raw[b] = qW @ key[b]^T  NT
    gemm_nt_mma<<<dim3(NK / 128, KQ / 128, BATCH), 128>>>(
        qW, key, att_ptr, DIM, DIM, DIM, NK,
        0L, (long)NK * DIM, (long)KQ * NK, 1.0f);

    // 3) mask + softmax in place
    mask_softmax<<<BATCH * KQ, 256>>>(att_ptr, mask);

    // 4) out[b] = att[b] @ key[b]    NN
    gemm_nn_mma<<<dim3(DIM / 128, KQ / 128, BATCH), 128>>>(
        att_ptr, key, out_ptr, NK, NK, DIM, DIM,
        (long)KQ * NK, (long)NK * DIM, (long)KQ * DIM, 1.0f);
}

// round 8
// speedup vs baseline: 1.3761x; 1.3761x over previous
#include <cuda_runtime.h>
#include <cuda_bf16.h>
#include <math.h>
#include <stdint.h>

// Problem shapes (fixed by the reference)
#define BATCH 16
#define KQ    512
#define NK    2048
#define DIM   1024

// ---------------- scratch (no cudaMalloc allowed) ----------------
__device__ float g_qW[KQ * DIM];                    // 2 MB
__device__ float g_qW_part[8 * KQ * DIM];           // 16 MB split-K partials
__device__ float g_att_scratch[BATCH * KQ * NK];    // 64 MB (if att not in d_out)
__device__ int   g_mask_kind;                       // 0=int32, 1=uint8, 2=float32

// ---------------- helpers ----------------
__device__ __forceinline__ float rna_tf32(float x) {
    float y;
    asm("cvt.rna.tf32.f32 %0, %1;" : "=f"(y) : "f"(x));
    return y;
}
__device__ __forceinline__ float4 rna4(float4 v) {
    v.x = rna_tf32(v.x); v.y = rna_tf32(v.y);
    v.z = rna_tf32(v.z); v.w = rna_tf32(v.w);
    return v;
}
__device__ __forceinline__ void mma_tf32(float* c, const uint32_t* a, const uint32_t* b) {
    asm volatile(
        "mma.sync.aligned.m16n8k8.row.col.f32.tf32.tf32.f32 "
        "{%0,%1,%2,%3}, {%4,%5,%6,%7}, {%8,%9}, {%0,%1,%2,%3};"
        : "+f"(c[0]), "+f"(c[1]), "+f"(c[2]), "+f"(c[3])
        : "r"(a[0]), "r"(a[1]), "r"(a[2]), "r"(a[3]), "r"(b[0]), "r"(b[1]));
}

#define PAD 20     // 16 k-cols + 4 pad -> conflict-free fragment LDS
#define SBS 136    // NN B tile: 128 n-cols + 8 pad

// =====================================================================
// tf32 mma.sync GEMM, NT: C[M,N] = alpha * A[M,Kd] * B[N,Kd]^T
// Block 128x128, 4 warps (2x2), warp tile 64x64, K-chunk 16,
// 2-stage smem double buffer, one barrier per chunk.  (R6-verified)
// =====================================================================
__global__ void __launch_bounds__(128) gemm_nt_mma(
    const float* __restrict__ A, const float* __restrict__ B, float* __restrict__ C,
    int Kd, int lda, int ldb, int ldc, long sA, long sB, long sC, float alpha)
{
    __shared__ float As[2][128][PAD];
    __shared__ float Bs[2][128][PAD];

    const int tid  = threadIdx.x;
    const int wid  = tid >> 5;
    const int lane = tid & 31;
    const int wm   = wid & 1;        // 0..1 -> 64-row half
    const int wn   = wid >> 1;       // 0..1 -> 64-col half
    const int grp  = lane >> 2;      // 0..7
    const int tig  = lane & 3;       // 0..3

    A += (long)blockIdx.z * sA + (long)blockIdx.y * 128 * lda;
    B += (long)blockIdx.z * sB + (long)blockIdx.x * 128 * ldb;
    C += (long)blockIdx.z * sC + (long)blockIdx.y * 128 * ldc + (long)blockIdx.x * 128;

    const int trow = tid >> 2;          // 0..31  (+32*i)
    const int tseg = (tid & 3) * 4;     // 0,4,8,12

    float acc[4][8][4];
    #pragma unroll
    for (int i = 0; i < 4; i++)
        #pragma unroll
        for (int j = 0; j < 8; j++)
            #pragma unroll
            for (int t = 0; t < 4; t++) acc[i][j][t] = 0.f;

    const int NCH = Kd >> 4;
    float4 pa[4], pb[4];

    // prologue: chunk 0 -> stage 0
    #pragma unroll
    for (int i = 0; i < 4; i++) {
        pa[i] = *(const float4*)(A + (long)(trow + 32 * i) * lda + tseg);
        pb[i] = *(const float4*)(B + (long)(trow + 32 * i) * ldb + tseg);
    }
    #pragma unroll
    for (int i = 0; i < 4; i++) {
        *(float4*)&As[0][trow + 32 * i][tseg] = rna4(pa[i]);
        *(float4*)&Bs[0][trow + 32 * i][tseg] = rna4(pb[i]);
    }
    __syncthreads();

    for (int kc = 0; kc < NCH; kc++) {
        const int st = kc & 1;
        if (kc + 1 < NCH) {
            const float* An = A + (long)(kc + 1) * 16;
            const float* Bn = B + (long)(kc + 1) * 16;
            #pragma unroll
            for (int i = 0; i < 4; i++) {
                pa[i] = *(const float4*)(An + (long)(trow + 32 * i) * lda + tseg);
                pb[i] = *(const float4*)(Bn + (long)(trow + 32 * i) * ldb + tseg);
            }
        }

        #pragma unroll
        for (int ks = 0; ks < 2; ks++) {
            const int k0 = ks * 8;
            uint32_t afr[4][4], bfr[8][2];
            #pragma unroll
            for (int mt = 0; mt < 4; mt++) {
                int r0 = wm * 64 + mt * 16 + grp;
                afr[mt][0] = __float_as_uint(As[st][r0][k0 + tig]);
                afr[mt][1] = __float_as_uint(As[st][r0 + 8][k0 + tig]);
                afr[mt][2] = __float_as_uint(As[st][r0][k0 + tig + 4]);
                afr[mt][3] = __float_as_uint(As[st][r0 + 8][k0 + tig + 4]);
            }
            #pragma unroll
            for (int nt = 0; nt < 8; nt++) {
                int n0 = wn * 64 + nt * 8 + grp;
                bfr[nt][0] = __float_as_uint(Bs[st][n0][k0 + tig]);
                bfr[nt][1] = __float_as_uint(Bs[st][n0][k0 + tig + 4]);
            }
            #pragma unroll
            for (int mt = 0; mt < 4; mt++)
                #pragma unroll
                for (int nt = 0; nt < 8; nt++)
                    mma_tf32(acc[mt][nt], afr[mt], bfr[nt]);
        }

        if (kc + 1 < NCH) {
            const int sn = st ^ 1;
            #pragma unroll
            for (int i = 0; i < 4; i++) {
                *(float4*)&As[sn][trow + 32 * i][tseg] = rna4(pa[i]);
                *(float4*)&Bs[sn][trow + 32 * i][tseg] = rna4(pb[i]);
            }
        }
        __syncthreads();
    }

    #pragma unroll
    for (int mt = 0; mt < 4; mt++) {
        int r0 = wm * 64 + mt * 16 + grp;
        #pragma unroll
        for (int nt = 0; nt < 8; nt++) {
            int c0 = wn * 64 + nt * 8 + 2 * tig;
            float2 v0 = make_float2(acc[mt][nt][0] * alpha, acc[mt][nt][1] * alpha);
            float2 v1 = make_float2(acc[mt][nt][2] * alpha, acc[mt][nt][3] * alpha);
            *(float2*)(C + (long)r0 * ldc + c0)       = v0;
            *(float2*)(C + (long)(r0 + 8) * ldc + c0) = v1;
        }
    }
}

// =====================================================================
// tf32 mma.sync GEMM, NN: C[M,N] = alpha * A[M,Kd] * B[Kd,N]
// Same tiling; B tile [16 k][128 n] per stage.  (R6-verified)
// =====================================================================
__global__ void __launch_bounds__(128) gemm_nn_mma(
    const float* __restrict__ A, const float* __restrict__ B, float* __restrict__ C,
    int Kd, int lda, int ldb, int ldc, long sA, long sB, long sC, float alpha)
{
    __shared__ float As[2][128][PAD];
    __shared__ float Bs[2][16][SBS];

    const int tid  = threadIdx.x;
    const int wid  = tid >> 5;
    const int lane = tid & 31;
    const int wm   = wid & 1;
    const int wn   = wid >> 1;
    const int grp  = lane >> 2;
    const int tig  = lane & 3;

    A += (long)blockIdx.z * sA + (long)blockIdx.y * 128 * lda;
    B += (long)blockIdx.z * sB + (long)blockIdx.x * 128;
    C += (long)blockIdx.z * sC + (long)blockIdx.y * 128 * ldc + (long)blockIdx.x * 128;

    const int trow = tid >> 2;
    const int tseg = (tid & 3) * 4;
    const int brow = tid >> 5;          // 0..3 (+4*i)
    const int bcol = (tid & 31) * 4;    // 0..124

    float acc[4][8][4];
    #pragma unroll
    for (int i = 0; i < 4; i++)
        #pragma unroll
        for (int j = 0; j < 8; j++)
            #pragma unroll
            for (int t = 0; t < 4; t++) acc[i][j][t] = 0.f;

    const int NCH = Kd >> 4;
    float4 pa[4], pb[4];

    #pragma unroll
    for (int i = 0; i < 4; i++) {
        pa[i] = *(const float4*)(A + (long)(trow + 32 * i) * lda + tseg);
        pb[i] = *(const float4*)(B + (long)(brow + 4 * i) * ldb + bcol);
    }
    #pragma unroll
    for (int i = 0; i < 4; i++) {
        *(float4*)&As[0][trow + 32 * i][tseg] = rna4(pa[i]);
        *(float4*)&Bs[0][brow + 4 * i][bcol]  = rna4(pb[i]);
    }
    __syncthreads();

    for (int kc = 0; kc < NCH; kc++) {
        const int st = kc & 1;
        if (kc + 1 < NCH) {
            const float* An = A + (long)(kc + 1) * 16;
            const float* Bn = B + (long)(kc + 1) * 16 * ldb;
            #pragma unroll
            for (int i = 0; i < 4; i++) {
                pa[i] = *(const float4*)(An + (long)(trow + 32 * i) * lda + tseg);
                pb[i] = *(const float4*)(Bn + (long)(brow + 4 * i) * ldb + bcol);
            }
        }

        #pragma unroll
        for (int ks = 0; ks < 2; ks++) {
            const int k0 = ks * 8;
            uint32_t afr[4][4], bfr[8][2];
            #pragma unroll
            for (int mt = 0; mt < 4; mt++) {
                int r0 = wm * 64 + mt * 16 + grp;
                afr[mt][0] = __float_as_uint(As[st][r0][k0 + tig]);
                afr[mt][1] = __float_as_uint(As[st][r0 + 8][k0 + tig]);
                afr[mt][2] = __float_as_uint(As[st][r0][k0 + tig + 4]);
                afr[mt][3] = __float_as_uint(As[st][r0 + 8][k0 + tig + 4]);
            }
            #pragma unroll
            for (int nt = 0; nt < 8; nt++) {
                int n0 = wn * 64 + nt * 8 + grp;
                bfr[nt][0] = __float_as_uint(Bs[st][k0 + tig][n0]);
                bfr[nt][1] = __float_as_uint(Bs[st][k0 + tig + 4][n0]);
            }
            #pragma unroll
            for (int mt = 0; mt < 4; mt++)
                #pragma unroll
                for (int nt = 0; nt < 8; nt++)
                    mma_tf32(acc[mt][nt], afr[mt], bfr[nt]);
        }

        if (kc + 1 < NCH) {
            const int sn = st ^ 1;
            #pragma unroll
            for (int i = 0; i < 4; i++) {
                *(float4*)&As[sn][trow + 32 * i][tseg] = rna4(pa[i]);
                *(float4*)&Bs[sn][brow + 4 * i][bcol]  = rna4(pb[i]);
            }
        }
        __syncthreads();
    }

    #pragma unroll
    for (int mt = 0; mt < 4; mt++) {
        int r0 = wm * 64 + mt * 16 + grp;
        #pragma unroll
        for (int nt = 0; nt < 8; nt++) {
            int c0 = wn * 64 + nt * 8 + 2 * tig;
            float2 v0 = make_float2(acc[mt][nt][0] * alpha, acc[mt][nt][1] * alpha);
            float2 v1 = make_float2(acc[mt][nt][2] * alpha, acc[mt][nt][3] * alpha);
            *(float2*)(C + (long)r0 * ldc + c0)       = v0;
            *(float2*)(C + (long)(r0 + 8) * ldc + c0) = v1;
        }
    }
}

// ---------------- split-K reduction for qW ----------------
__global__ void __launch_bounds__(256) reduce_qw(
    const float* __restrict__ part, float* __restrict__ qW)
{
    int i = (blockIdx.x * 256 + threadIdx.x) * 4;
    float4 s = make_float4(0.f, 0.f, 0.f, 0.f);
    #pragma unroll
    for (int z = 0; z < 8; z++) {
        float4 v = *(const float4*)(part + (long)z * (KQ * DIM) + i);
        s.x += v.x; s.y += v.y; s.z += v.z; s.w += v.w;
    }
    const float a = 1.0f / 32.0f;
    s.x *= a; s.y *= a; s.z *= a; s.w *= a;
    *(float4*)(qW + i) = s;
}

// ---------------- mask dtype detection ----------------
__global__ void detect_mask_kind(const unsigned char* __restrict__ m)
{
    if (threadIdx.x != 0 || blockIdx.x != 0) return;
    int cnt[4] = {0, 0, 0, 0};
    for (int i = 0; i < 4096; i++)
        if (m[i] != 0) cnt[i & 3]++;
    int kind;
    if (cnt[1] > 0)                    kind = 1;  // uint8 bool
    else if (cnt[2] > 0 || cnt[3] > 0) kind = 2;  // float32
    else                               kind = 0;  // int32 bool
    g_mask_kind = kind;
}

// ---------------- fused mask + softmax ----------------
__global__ void __launch_bounds__(256) mask_softmax(
    float* __restrict__ att, const void* __restrict__ mask_raw)
{
    long row = blockIdx.x;
    float* p = att + row * (long)NK;
    int tid = threadIdx.x;
    int kind = g_mask_kind;

    const unsigned char* m8  = (const unsigned char*)mask_raw + row * (long)NK;
    const int*           m32 = (const int*)mask_raw           + row * (long)NK;
    const float*         mf  = (const float*)mask_raw         + row * (long)NK;

    float v[8];
    float lmax = -INFINITY;
    #pragma unroll
    for (int i = 0; i < 8; i++) {
        int idx = tid + i * 256;
        bool keep;
        if (kind == 0)      keep = (m32[idx] != 0);
        else if (kind == 1) keep = (m8[idx] != 0);
        else                keep = (mf[idx] != 0.0f);
        float s = keep ? p[idx] : -INFINITY;
        v[i] = s;
        lmax = fmaxf(lmax, s);
    }

    __shared__ float red[8];
    #pragma unroll
    for (int o = 16; o > 0; o >>= 1)
        lmax = fmaxf(lmax, __shfl_xor_sync(0xffffffffu, lmax, o));
    if ((tid & 31) == 0) red[tid >> 5] = lmax;
    __syncthreads();
    float rmax = fmaxf(fmaxf(fmaxf(red[0], red[1]), fmaxf(red[2], red[3])),
                       fmaxf(fmaxf(red[4], red[5]), fmaxf(red[6], red[7])));
    __syncthreads();

    float lsum = 0.f;
    #pragma unroll
    for (int i = 0; i < 8; i++) {
        float e = (v[i] == -INFINITY) ? 0.f : __expf(v[i] - rmax);
        v[i] = e;
        lsum += e;
    }
    #pragma unroll
    for (int o = 16; o > 0; o >>= 1)
        lsum += __shfl_xor_sync(0xffffffffu, lsum, o);
    if ((tid & 31) == 0) red[tid >> 5] = lsum;
    __syncthreads();
    float rsum = red[0] + red[1] + red[2] + red[3] + red[4] + red[5] + red[6] + red[7];
    float inv = (rsum > 0.f) ? (1.f / rsum) : 0.f;

    #pragma unroll
    for (int i = 0; i < 8; i++) p[tid + i * 256] = v[i] * inv;
}

// ---------------- launcher ----------------
extern "C" void kernel_launch(void* const* d_in, const int* in_sizes, int n_in,
                              void* d_out, int out_size)
{
    const float* query = (const float*)d_in[0];   // [KQ, DIM]
    const float* key   = (const float*)d_in[1];   // [BATCH, NK, DIM]
    const float* W     = (const float*)d_in[2];   // [DIM, DIM]
    const void*  mask  = d_in[3];                 // [BATCH, KQ, NK] bool

    float* out_ptr = (float*)d_out;
    const long outBKD = (long)BATCH * KQ * DIM;

    float *qW, *qW_part;
    cudaGetSymbolAddress((void**)&qW, g_qW);
    cudaGetSymbolAddress((void**)&qW_part, g_qW_part);
    float* att_ptr;
    if ((long)out_size > outBKD) {
        att_ptr = out_ptr + outBKD;
    } else {
        cudaGetSymbolAddress((void**)&att_ptr, g_att_scratch);
    }

    // 0) mask dtype detection
    detect_mask_kind<<<1, 1>>>((const unsigned char*)mask);

    // 1) qW partials via split-K=8 (256 CTAs), then deterministic reduce (/32)
    gemm_nn_mma<<<dim3(DIM / 128, KQ / 128, 8), 128>>>(
        query, W, qW_part, 128, DIM, DIM, DIM,
        128L, 128L * DIM, (long)KQ * DIM, 1.0f);
    reduce_qw<<<KQ * DIM / (256 * 4), 256>>>(qW_part, qW);

    // 2) att_raw[b] = qW @ key[b]^T  NT
    gemm_nt_mma<<<dim3(NK / 128, KQ / 128, BATCH), 128>>>(
        qW, key, att_ptr, DIM, DIM, DIM, NK,
        0L, (long)NK * DIM, (long)KQ * NK, 1.0f);

    // 3) mask + softmax in place
    mask_softmax<<<BATCH * KQ, 256>>>(att_ptr, mask);

    // 4) out[b] = att[b] @ key[b]    NN
    gemm_nn_mma<<<dim3(DIM / 128, KQ / 128, BATCH), 128>>>(
        att_ptr, key, out_ptr, NK, NK, DIM, DIM,
        (long)KQ * NK, (long)NK * DIM, (long)KQ * DIM, 1.0f);
}

// round 9
// speedup vs baseline: 2.1218x; 1.5419x over previous
#include <cuda_runtime.h>
#include <cuda_fp16.h>
#include <math.h>
#include <stdint.h>

// Problem shapes (fixed by the reference)
#define BATCH 16
#define KQ    512
#define NK    2048
#define DIM   1024

// ---------------- scratch (no cudaMalloc allowed) ----------------
__device__ float  g_qW_part[8 * KQ * DIM];              // 16 MB split-K partials
__device__ __half g_qW_h[KQ * DIM];                     // 1 MB
__device__ __half g_query_h[KQ * DIM];                  // 1 MB
__device__ __half g_WT_h[DIM * DIM];                    // 2 MB  W^T [j][d]
__device__ __half g_key_h[(size_t)BATCH * NK * DIM];    // 64 MB key as-is (half)
__device__ __half g_keyT_h[(size_t)BATCH * DIM * NK];   // 64 MB key^T per batch [d][n]
__device__ float  g_att_scratch[(size_t)BATCH * KQ * NK]; // 64 MB (if att not in d_out)
__device__ __half g_att_h[(size_t)BATCH * KQ * NK];     // 64 MB half att
__device__ int    g_mask_kind;                          // 0=int32, 1=uint8, 2=float32

// ---------------- helpers ----------------
__device__ __forceinline__ void cp16(uint32_t s, const void* g) {
    asm volatile("cp.async.cg.shared.global [%0], [%1], 16;" :: "r"(s), "l"(g));
}
__device__ __forceinline__ void cp_commit() {
    asm volatile("cp.async.commit_group;" ::: "memory");
}
__device__ __forceinline__ void cp_wait0() {
    asm volatile("cp.async.wait_group 0;" ::: "memory");
}
__device__ __forceinline__ void mma_f16(float* c, uint32_t a0, uint32_t a1,
                                        uint32_t a2, uint32_t a3,
                                        uint32_t b0, uint32_t b1) {
    asm volatile(
        "mma.sync.aligned.m16n8k16.row.col.f32.f16.f16.f32 "
        "{%0,%1,%2,%3}, {%4,%5,%6,%7}, {%8,%9}, {%0,%1,%2,%3};"
        : "+f"(c[0]), "+f"(c[1]), "+f"(c[2]), "+f"(c[3])
        : "r"(a0), "r"(a1), "r"(a2), "r"(a3), "r"(b0), "r"(b1));
}

// Tile row stride in halfs: 32 data + 8 pad = 40 (80 B; conflict-free LDS.32
// fragment access: word = 20*row + tig (+const) covers all 32 banks).
#define HST 40

// =====================================================================
// fp16 mma.sync GEMM, NT: C[M,N] = A[M,Kd] * B[N,Kd]^T  (both K-contig half)
// Block 128x128, 4 warps (2x2), warp tile 64x64, K-chunk 32 halfs,
// 2-stage cp.async double buffer, one barrier per chunk.
// =====================================================================
__global__ void __launch_bounds__(128) gemm_nt_h(
    const __half* __restrict__ A, const __half* __restrict__ B, float* __restrict__ C,
    int Kd, int lda, int ldb, int ldc, long sA, long sB, long sC)
{
    __shared__ __half As[2][128 * HST];
    __shared__ __half Bs[2][128 * HST];

    const int tid  = threadIdx.x;
    const int wid  = tid >> 5;
    const int lane = tid & 31;
    const int wm   = wid & 1;        // 64-row half
    const int wn   = wid >> 1;       // 64-col half
    const int grp  = lane >> 2;      // 0..7
    const int tig  = lane & 3;       // 0..3

    A += (long)blockIdx.z * sA + (long)blockIdx.y * 128 * lda;
    B += (long)blockIdx.z * sB + (long)blockIdx.x * 128 * ldb;
    C += (long)blockIdx.z * sC + (long)blockIdx.y * 128 * ldc + (long)blockIdx.x * 128;

    const int crow = tid >> 2;          // 0..31 (+32*i)
    const int cseg = (tid & 3) * 8;     // half offset of 16B segment

    float acc[4][8][4];
    #pragma unroll
    for (int i = 0; i < 4; i++)
        #pragma unroll
        for (int j = 0; j < 8; j++)
            #pragma unroll
            for (int t = 0; t < 4; t++) acc[i][j][t] = 0.f;

    const int NCH = Kd >> 5;

    uint32_t sa_base[2], sb_base[2];
    #pragma unroll
    for (int s = 0; s < 2; s++) {
        sa_base[s] = (uint32_t)__cvta_generic_to_shared(&As[s][0]);
        sb_base[s] = (uint32_t)__cvta_generic_to_shared(&Bs[s][0]);
    }

    // prologue: chunk 0 -> stage 0
    #pragma unroll
    for (int i = 0; i < 4; i++) {
        int row = crow + 32 * i;
        uint32_t d = (uint32_t)(row * HST + cseg) * 2;
        cp16(sa_base[0] + d, A + (long)row * lda + cseg);
        cp16(sb_base[0] + d, B + (long)row * ldb + cseg);
    }
    cp_commit();

    for (int kc = 0; kc < NCH; kc++) {
        cp_wait0();
        __syncthreads();

        if (kc + 1 < NCH) {
            const int sn = (kc + 1) & 1;
            const __half* An = A + (long)(kc + 1) * 32;
            const __half* Bn = B + (long)(kc + 1) * 32;
            #pragma unroll
            for (int i = 0; i < 4; i++) {
                int row = crow + 32 * i;
                uint32_t d = (uint32_t)(row * HST + cseg) * 2;
                cp16(sa_base[sn] + d, An + (long)row * lda + cseg);
                cp16(sb_base[sn] + d, Bn + (long)row * ldb + cseg);
            }
            cp_commit();
        }

        const int st = kc & 1;
        #pragma unroll
        for (int g = 0; g < 2; g++) {       // two k16 groups in the 32-chunk
            const int k0 = 16 * g + 2 * tig;
            uint32_t afr[4][4], bfr[8][2];
            #pragma unroll
            for (int mt = 0; mt < 4; mt++) {
                int r0 = wm * 64 + mt * 16 + grp;
                afr[mt][0] = *(const uint32_t*)&As[st][r0 * HST + k0];
                afr[mt][1] = *(const uint32_t*)&As[st][(r0 + 8) * HST + k0];
                afr[mt][2] = *(const uint32_t*)&As[st][r0 * HST + k0 + 8];
                afr[mt][3] = *(const uint32_t*)&As[st][(r0 + 8) * HST + k0 + 8];
            }
            #pragma unroll
            for (int nt = 0; nt < 8; nt++) {
                int n0 = wn * 64 + nt * 8 + grp;
                bfr[nt][0] = *(const uint32_t*)&Bs[st][n0 * HST + k0];
                bfr[nt][1] = *(const uint32_t*)&Bs[st][n0 * HST + k0 + 8];
            }
            #pragma unroll
            for (int mt = 0; mt < 4; mt++)
                #pragma unroll
                for (int nt = 0; nt < 8; nt++)
                    mma_f16(acc[mt][nt], afr[mt][0], afr[mt][1], afr[mt][2], afr[mt][3],
                            bfr[nt][0], bfr[nt][1]);
        }
        __syncthreads();
    }

    #pragma unroll
    for (int mt = 0; mt < 4; mt++) {
        int r0 = wm * 64 + mt * 16 + grp;
        #pragma unroll
        for (int nt = 0; nt < 8; nt++) {
            int c0 = wn * 64 + nt * 8 + 2 * tig;
            *(float2*)(C + (long)r0 * ldc + c0)       = make_float2(acc[mt][nt][0], acc[mt][nt][1]);
            *(float2*)(C + (long)(r0 + 8) * ldc + c0) = make_float2(acc[mt][nt][2], acc[mt][nt][3]);
        }
    }
}

// ---------------- conversion kernels ----------------
__global__ void __launch_bounds__(256) f32_to_f16_vec(
    const float* __restrict__ src, __half* __restrict__ dst)
{
    int i = blockIdx.x * 256 + threadIdx.x;
    float4 v = ((const float4*)src)[i];
    ((__half2*)dst)[2 * i]     = __floats2half2_rn(v.x, v.y);
    ((__half2*)dst)[2 * i + 1] = __floats2half2_rn(v.z, v.w);
}

// dst[C][R] (half) = src[R][C]^T (f32)
__global__ void __launch_bounds__(256) transpose_f16(
    const float* __restrict__ src, __half* __restrict__ dst, int R, int C)
{
    __shared__ float t[32][33];
    int c0 = blockIdx.x * 32, r0 = blockIdx.y * 32;
    int x = threadIdx.x, y = threadIdx.y;
    #pragma unroll
    for (int i = 0; i < 32; i += 8)
        t[y + i][x] = src[(long)(r0 + y + i) * C + c0 + x];
    __syncthreads();
    #pragma unroll
    for (int i = 0; i < 32; i += 8)
        dst[(long)(c0 + y + i) * R + r0 + x] = __float2half(t[x][y + i]);
}

// key [B][N][D] f32 -> key_h (same layout, half) + keyT_h [B][D][N] (half)
__global__ void __launch_bounds__(256) key_dual(
    const float* __restrict__ key, __half* __restrict__ key_h, __half* __restrict__ keyT_h)
{
    __shared__ float t[32][33];
    long b = blockIdx.z;
    const float* s = key + b * (long)NK * DIM;
    __half* d1 = key_h + b * (long)NK * DIM;
    __half* d2 = keyT_h + b * (long)DIM * NK;
    int d0 = blockIdx.x * 32, n0 = blockIdx.y * 32;
    int x = threadIdx.x, y = threadIdx.y;
    #pragma unroll
    for (int i = 0; i < 32; i += 8) {
        float v = s[(long)(n0 + y + i) * DIM + d0 + x];
        t[y + i][x] = v;
        d1[(long)(n0 + y + i) * DIM + d0 + x] = __float2half(v);
    }
    __syncthreads();
    #pragma unroll
    for (int i = 0; i < 32; i += 8)
        d2[(long)(d0 + y + i) * NK + n0 + x] = __float2half(t[x][y + i]);
}

// ---------------- split-K reduction for qW (writes half) ----------------
__global__ void __launch_bounds__(256) reduce_qw(
    const float* __restrict__ part, __half* __restrict__ qW_h)
{
    int i = (blockIdx.x * 256 + threadIdx.x) * 4;
    float4 s = make_float4(0.f, 0.f, 0.f, 0.f);
    #pragma unroll
    for (int z = 0; z < 8; z++) {
        float4 v = *(const float4*)(part + (long)z * (KQ * DIM) + i);
        s.x += v.x; s.y += v.y; s.z += v.z; s.w += v.w;
    }
    const float a = 1.0f / 32.0f;
    ((__half2*)qW_h)[i / 2]     = __floats2half2_rn(s.x * a, s.y * a);
    ((__half2*)qW_h)[i / 2 + 1] = __floats2half2_rn(s.z * a, s.w * a);
}

// ---------------- mask dtype detection ----------------
__global__ void detect_mask_kind(const unsigned char* __restrict__ m)
{
    if (threadIdx.x != 0 || blockIdx.x != 0) return;
    int cnt[4] = {0, 0, 0, 0};
    for (int i = 0; i < 4096; i++)
        if (m[i] != 0) cnt[i & 3]++;
    int kind;
    if (cnt[1] > 0)                    kind = 1;  // uint8 bool
    else if (cnt[2] > 0 || cnt[3] > 0) kind = 2;  // float32
    else                               kind = 0;  // int32 bool
    g_mask_kind = kind;
}

// ---------------- fused mask + softmax (writes fp32 att + half att) --------
__global__ void __launch_bounds__(256) mask_softmax(
    float* __restrict__ att, __half* __restrict__ att_h, const void* __restrict__ mask_raw)
{
    long row = blockIdx.x;
    float* p = att + row * (long)NK;
    __half* ph = att_h + row * (long)NK;
    int tid = threadIdx.x;
    int kind = g_mask_kind;

    const unsigned char* m8  = (const unsigned char*)mask_raw + row * (long)NK;
    const int*           m32 = (const int*)mask_raw           + row * (long)NK;
    const float*         mf  = (const float*)mask_raw         + row * (long)NK;

    float v[8];
    float lmax = -INFINITY;
    #pragma unroll
    for (int i = 0; i < 8; i++) {
        int idx = tid + i * 256;
        bool keep;
        if (kind == 0)      keep = (m32[idx] != 0);
        else if (kind == 1) keep = (m8[idx] != 0);
        else                keep = (mf[idx] != 0.0f);
        float s = keep ? p[idx] : -INFINITY;
        v[i] = s;
        lmax = fmaxf(lmax, s);
    }

    __shared__ float red[8];
    #pragma unroll
    for (int o = 16; o > 0; o >>= 1)
        lmax = fmaxf(lmax, __shfl_xor_sync(0xffffffffu, lmax, o));
    if ((tid & 31) == 0) red[tid >> 5] = lmax;
    __syncthreads();
    float rmax = fmaxf(fmaxf(fmaxf(red[0], red[1]), fmaxf(red[2], red[3])),
                       fmaxf(fmaxf(red[4], red[5]), fmaxf(red[6], red[7])));
    __syncthreads();

    float lsum = 0.f;
    #pragma unroll
    for (int i = 0; i < 8; i++) {
        float e = (v[i] == -INFINITY) ? 0.f : __expf(v[i] - rmax);
        v[i] = e;
        lsum += e;
    }
    #pragma unroll
    for (int o = 16; o > 0; o >>= 1)
        lsum += __shfl_xor_sync(0xffffffffu, lsum, o);
    if ((tid & 31) == 0) red[tid >> 5] = lsum;
    __syncthreads();
    float rsum = red[0] + red[1] + red[2] + red[3] + red[4] + red[5] + red[6] + red[7];
    float inv = (rsum > 0.f) ? (1.f / rsum) : 0.f;

    #pragma unroll
    for (int i = 0; i < 8; i++) {
        float r = v[i] * inv;
        int idx = tid + i * 256;
        p[idx] = r;
        ph[idx] = __float2half(r);
    }
}

// ---------------- launcher ----------------
extern "C" void kernel_launch(void* const* d_in, const int* in_sizes, int n_in,
                              void* d_out, int out_size)
{
    const float* query = (const float*)d_in[0];   // [KQ, DIM]
    const float* key   = (const float*)d_in[1];   // [BATCH, NK, DIM]
    const float* W     = (const float*)d_in[2];   // [DIM, DIM]
    const void*  mask  = d_in[3];                 // [BATCH, KQ, NK] bool

    float* out_ptr = (float*)d_out;
    const long outBKD = (long)BATCH * KQ * DIM;

    float *qW_part, *att_scratch;
    __half *qW_h, *query_h, *WT_h, *key_h, *keyT_h, *att_h;
    cudaGetSymbolAddress((void**)&qW_part, g_qW_part);
    cudaGetSymbolAddress((void**)&qW_h, g_qW_h);
    cudaGetSymbolAddress((void**)&query_h, g_query_h);
    cudaGetSymbolAddress((void**)&WT_h, g_WT_h);
    cudaGetSymbolAddress((void**)&key_h, g_key_h);
    cudaGetSymbolAddress((void**)&keyT_h, g_keyT_h);
    cudaGetSymbolAddress((void**)&att_h, g_att_h);
    cudaGetSymbolAddress((void**)&att_scratch, g_att_scratch);

    float* att_ptr = ((long)out_size > outBKD) ? (out_ptr + outBKD) : att_scratch;

    // 0) mask dtype detection
    detect_mask_kind<<<1, 1>>>((const unsigned char*)mask);

    // 1) conversions: query -> half, W -> W^T half, key -> (key_h, keyT_h)
    f32_to_f16_vec<<<(KQ * DIM / 4) / 256, 256>>>(query, query_h);
    transpose_f16<<<dim3(DIM / 32, DIM / 32), dim3(32, 8)>>>(W, WT_h, DIM, DIM);
    key_dual<<<dim3(DIM / 32, NK / 32, BATCH), dim3(32, 8)>>>(key, key_h, keyT_h);

    // 2) qW partials via split-K=8 (NT: A=query_h, B=WT_h), then reduce (/32) -> half
    gemm_nt_h<<<dim3(DIM / 128, KQ / 128, 8), 128>>>(
        query_h, WT_h, qW_part, 128, DIM, DIM, DIM,
        128L, 128L, (long)KQ * DIM);
    reduce_qw<<<KQ * DIM / (256 * 4), 256>>>(qW_part, qW_h);

    // 3) scores[b] = qW_h @ key_h[b]^T   (NT)
    gemm_nt_h<<<dim3(NK / 128, KQ / 128, BATCH), 128>>>(
        qW_h, key_h, att_ptr, DIM, DIM, DIM, NK,
        0L, (long)NK * DIM, (long)KQ * NK);

    // 4) mask + softmax in place (fp32 out) + half copy
    mask_softmax<<<BATCH * KQ, 256>>>(att_ptr, att_h, mask);

    // 5) out[b] = att_h[b] @ keyT_h[b]^T (NT over n)
    gemm_nt_h<<<dim3(DIM / 128, KQ / 128, BATCH), 128>>>(
        att_h, keyT_h, out_ptr, NK, NK, NK, DIM,
        (long)KQ * NK, (long)DIM * NK, (long)KQ * DIM);
}

// round 10
// speedup vs baseline: 2.2359x; 1.0537x over previous
#include <cuda_runtime.h>
#include <cuda_fp16.h>
#include <math.h>
#include <stdint.h>

// Problem shapes (fixed by the reference)
#define BATCH 16
#define KQ    512
#define NK    2048
#define DIM   1024

// ---------------- scratch (no cudaMalloc allowed) ----------------
__device__ float  g_qW_part[8 * KQ * DIM];              // 16 MB split-K partials
__device__ __half g_qW_h[KQ * DIM];                     // 1 MB
__device__ __half g_query_h[KQ * DIM];                  // 1 MB
__device__ __half g_WT_h[DIM * DIM];                    // 2 MB  W^T [j][d]
__device__ __half g_key_h[(size_t)BATCH * NK * DIM];    // 64 MB key (half, native layout)
__device__ float  g_att_scratch[(size_t)BATCH * KQ * NK]; // 64 MB (if att not in d_out)
__device__ __half g_att_h[(size_t)BATCH * KQ * NK];     // 64 MB half att
__device__ int    g_mask_kind;                          // 0=int32, 1=uint8, 2=float32

// ---------------- helpers ----------------
__device__ __forceinline__ void cp16(uint32_t s, const void* g) {
    asm volatile("cp.async.cg.shared.global [%0], [%1], 16;" :: "r"(s), "l"(g));
}
__device__ __forceinline__ void cp_commit() {
    asm volatile("cp.async.commit_group;" ::: "memory");
}
__device__ __forceinline__ void cp_wait0() {
    asm volatile("cp.async.wait_group 0;" ::: "memory");
}
__device__ __forceinline__ void mma_f16(float* c, uint32_t a0, uint32_t a1,
                                        uint32_t a2, uint32_t a3,
                                        uint32_t b0, uint32_t b1) {
    asm volatile(
        "mma.sync.aligned.m16n8k16.row.col.f32.f16.f16.f32 "
        "{%0,%1,%2,%3}, {%4,%5,%6,%7}, {%8,%9}, {%0,%1,%2,%3};"
        : "+f"(c[0]), "+f"(c[1]), "+f"(c[2]), "+f"(c[3])
        : "r"(a0), "r"(a1), "r"(a2), "r"(a3), "r"(b0), "r"(b1));
}
__device__ __forceinline__ void ldsm4(uint32_t* r, uint32_t a) {
    asm volatile("ldmatrix.sync.aligned.m8n8.x4.shared.b16 {%0,%1,%2,%3}, [%4];"
        : "=r"(r[0]), "=r"(r[1]), "=r"(r[2]), "=r"(r[3]) : "r"(a));
}
__device__ __forceinline__ void ldsm4t(uint32_t* r, uint32_t a) {
    asm volatile("ldmatrix.sync.aligned.m8n8.x4.trans.shared.b16 {%0,%1,%2,%3}, [%4];"
        : "=r"(r[0]), "=r"(r[1]), "=r"(r[2]), "=r"(r[3]) : "r"(a));
}

#define HST 40    // A / NT-B tile row stride (halfs): 32 data + 8 pad
#define SBN 136   // NN-B tile row stride (halfs): 128 data + 8 pad

// =====================================================================
// fp16 mma GEMM, NT: C[M,N] = A[M,Kd] * B[N,Kd]^T  (both K-contig half)
// Block 128x128, 4 warps (2x2), warp tile 64x64, K-chunk 32 halfs,
// 2-stage cp.async double buffer, ldmatrix fragment loads.
// =====================================================================
__global__ void __launch_bounds__(128) gemm_nt_h(
    const __half* __restrict__ A, const __half* __restrict__ B, float* __restrict__ C,
    int Kd, int lda, int ldb, int ldc, long sA, long sB, long sC)
{
    __shared__ __half As[2][128 * HST];
    __shared__ __half Bs[2][128 * HST];

    const int tid  = threadIdx.x;
    const int wid  = tid >> 5;
    const int lane = tid & 31;
    const int wm   = wid & 1;
    const int wn   = wid >> 1;
    const int grp  = lane >> 2;
    const int tig  = lane & 3;

    A += (long)blockIdx.z * sA + (long)blockIdx.y * 128 * lda;
    B += (long)blockIdx.z * sB + (long)blockIdx.x * 128 * ldb;
    C += (long)blockIdx.z * sC + (long)blockIdx.y * 128 * ldc + (long)blockIdx.x * 128;

    const int crow = tid >> 2;          // cp.async row 0..31 (+32*i)
    const int cseg = (tid & 3) * 8;     // 16B segment (halfs)

    const uint32_t sa0 = (uint32_t)__cvta_generic_to_shared(&As[0][0]);
    const uint32_t sb0 = (uint32_t)__cvta_generic_to_shared(&Bs[0][0]);
    const uint32_t stgA = (uint32_t)(128 * HST * 2);

    // ldmatrix per-lane base offsets (bytes), stage 0, k-group 0
    const uint32_t offA = (uint32_t)(((wm * 64 + (lane & 15)) * HST + 8 * (lane >> 4)) * 2);
    const uint32_t offB = (uint32_t)(((wn * 64 + (lane & 7) + 8 * (lane >> 4)) * HST
                                      + 8 * ((lane >> 3) & 1)) * 2);

    float acc[4][8][4];
    #pragma unroll
    for (int i = 0; i < 4; i++)
        #pragma unroll
        for (int j = 0; j < 8; j++)
            #pragma unroll
            for (int t = 0; t < 4; t++) acc[i][j][t] = 0.f;

    const int NCH = Kd >> 5;

    // prologue: chunk 0 -> stage 0
    #pragma unroll
    for (int i = 0; i < 4; i++) {
        int row = crow + 32 * i;
        uint32_t d = (uint32_t)(row * HST + cseg) * 2;
        cp16(sa0 + d, A + (long)row * lda + cseg);
        cp16(sb0 + d, B + (long)row * ldb + cseg);
    }
    cp_commit();

    for (int kc = 0; kc < NCH; kc++) {
        cp_wait0();
        __syncthreads();

        if (kc + 1 < NCH) {
            const uint32_t so = ((kc + 1) & 1) * stgA;
            const __half* An = A + (long)(kc + 1) * 32;
            const __half* Bn = B + (long)(kc + 1) * 32;
            #pragma unroll
            for (int i = 0; i < 4; i++) {
                int row = crow + 32 * i;
                uint32_t d = (uint32_t)(row * HST + cseg) * 2;
                cp16(sa0 + so + d, An + (long)row * lda + cseg);
                cp16(sb0 + so + d, Bn + (long)row * ldb + cseg);
            }
            cp_commit();
        }

        const uint32_t so = (kc & 1) * stgA;
        #pragma unroll
        for (int g = 0; g < 2; g++) {
            uint32_t afr[4][4], bfr[4][4];
            #pragma unroll
            for (int mt = 0; mt < 4; mt++)
                ldsm4(afr[mt], sa0 + so + offA + (uint32_t)(mt * 16 * HST * 2 + g * 32));
            #pragma unroll
            for (int np = 0; np < 4; np++)
                ldsm4(bfr[np], sb0 + so + offB + (uint32_t)(np * 16 * HST * 2 + g * 32));
            #pragma unroll
            for (int mt = 0; mt < 4; mt++)
                #pragma unroll
                for (int np = 0; np < 4; np++) {
                    mma_f16(acc[mt][2 * np],     afr[mt][0], afr[mt][1], afr[mt][2], afr[mt][3],
                            bfr[np][0], bfr[np][1]);
                    mma_f16(acc[mt][2 * np + 1], afr[mt][0], afr[mt][1], afr[mt][2], afr[mt][3],
                            bfr[np][2], bfr[np][3]);
                }
        }
        __syncthreads();
    }

    #pragma unroll
    for (int mt = 0; mt < 4; mt++) {
        int r0 = wm * 64 + mt * 16 + grp;
        #pragma unroll
        for (int nt = 0; nt < 8; nt++) {
            int c0 = wn * 64 + nt * 8 + 2 * tig;
            *(float2*)(C + (long)r0 * ldc + c0)       = make_float2(acc[mt][nt][0], acc[mt][nt][1]);
            *(float2*)(C + (long)(r0 + 8) * ldc + c0) = make_float2(acc[mt][nt][2], acc[mt][nt][3]);
        }
    }
}

// =====================================================================
// fp16 mma GEMM, NN: C[M,N] = A[M,Kd] * B[Kd,N]  (B row-major half)
// B tile [32 k][128 n], fragments via ldmatrix.trans.
// =====================================================================
__global__ void __launch_bounds__(128) gemm_nn_h(
    const __half* __restrict__ A, const __half* __restrict__ B, float* __restrict__ C,
    int Kd, int lda, int ldb, int ldc, long sA, long sB, long sC)
{
    __shared__ __half As[2][128 * HST];
    __shared__ __half Bs[2][32 * SBN];

    const int tid  = threadIdx.x;
    const int wid  = tid >> 5;
    const int lane = tid & 31;
    const int wm   = wid & 1;
    const int wn   = wid >> 1;
    const int grp  = lane >> 2;
    const int tig  = lane & 3;

    A += (long)blockIdx.z * sA + (long)blockIdx.y * 128 * lda;
    B += (long)blockIdx.z * sB + (long)blockIdx.x * 128;
    C += (long)blockIdx.z * sC + (long)blockIdx.y * 128 * ldc + (long)blockIdx.x * 128;

    const int crow = tid >> 2;          // A cp rows
    const int cseg = (tid & 3) * 8;
    const int brow = tid >> 4;          // B cp rows 0..7 (+8*i)
    const int bseg = (tid & 15) * 8;    // B cp col halfs

    const uint32_t sa0 = (uint32_t)__cvta_generic_to_shared(&As[0][0]);
    const uint32_t sb0 = (uint32_t)__cvta_generic_to_shared(&Bs[0][0]);
    const uint32_t stgA = (uint32_t)(128 * HST * 2);
    const uint32_t stgB = (uint32_t)(32 * SBN * 2);

    const uint32_t offA = (uint32_t)(((wm * 64 + (lane & 15)) * HST + 8 * (lane >> 4)) * 2);
    // NN-B trans: k-row = (l&7) + 8*((l>>3)&1), n-col = wn*64 + 8*(l>>4)
    const uint32_t offB = (uint32_t)((((lane & 7) + 8 * ((lane >> 3) & 1)) * SBN
                                      + wn * 64 + 8 * (lane >> 4)) * 2);

    float acc[4][8][4];
    #pragma unroll
    for (int i = 0; i < 4; i++)
        #pragma unroll
        for (int j = 0; j < 8; j++)
            #pragma unroll
            for (int t = 0; t < 4; t++) acc[i][j][t] = 0.f;

    const int NCH = Kd >> 5;

    #pragma unroll
    for (int i = 0; i < 4; i++) {
        int arow = crow + 32 * i;
        cp16(sa0 + (uint32_t)(arow * HST + cseg) * 2, A + (long)arow * lda + cseg);
        int kr = brow + 8 * i;
        cp16(sb0 + (uint32_t)(kr * SBN + bseg) * 2, B + (long)kr * ldb + bseg);
    }
    cp_commit();

    for (int kc = 0; kc < NCH; kc++) {
        cp_wait0();
        __syncthreads();

        if (kc + 1 < NCH) {
            const uint32_t soA = ((kc + 1) & 1) * stgA;
            const uint32_t soB = ((kc + 1) & 1) * stgB;
            const __half* An = A + (long)(kc + 1) * 32;
            const __half* Bn = B + (long)(kc + 1) * 32 * ldb;
            #pragma unroll
            for (int i = 0; i < 4; i++) {
                int arow = crow + 32 * i;
                cp16(sa0 + soA + (uint32_t)(arow * HST + cseg) * 2, An + (long)arow * lda + cseg);
                int kr = brow + 8 * i;
                cp16(sb0 + soB + (uint32_t)(kr * SBN + bseg) * 2, Bn + (long)kr * ldb + bseg);
            }
            cp_commit();
        }

        const uint32_t soA = (kc & 1) * stgA;
        const uint32_t soB = (kc & 1) * stgB;
        #pragma unroll
        for (int g = 0; g < 2; g++) {
            uint32_t afr[4][4], bfr[4][4];
            #pragma unroll
            for (int mt = 0; mt < 4; mt++)
                ldsm4(afr[mt], sa0 + soA + offA + (uint32_t)(mt * 16 * HST * 2 + g * 32));
            #pragma unroll
            for (int np = 0; np < 4; np++)
                ldsm4t(bfr[np], sb0 + soB + offB + (uint32_t)(np * 32 + g * 16 * SBN * 2));
            #pragma unroll
            for (int mt = 0; mt < 4; mt++)
                #pragma unroll
                for (int np = 0; np < 4; np++) {
                    mma_f16(acc[mt][2 * np],     afr[mt][0], afr[mt][1], afr[mt][2], afr[mt][3],
                            bfr[np][0], bfr[np][1]);
                    mma_f16(acc[mt][2 * np + 1], afr[mt][0], afr[mt][1], afr[mt][2], afr[mt][3],
                            bfr[np][2], bfr[np][3]);
                }
        }
        __syncthreads();
    }

    #pragma unroll
    for (int mt = 0; mt < 4; mt++) {
        int r0 = wm * 64 + mt * 16 + grp;
        #pragma unroll
        for (int nt = 0; nt < 8; nt++) {
            int c0 = wn * 64 + nt * 8 + 2 * tig;
            *(float2*)(C + (long)r0 * ldc + c0)       = make_float2(acc[mt][nt][0], acc[mt][nt][1]);
            *(float2*)(C + (long)(r0 + 8) * ldc + c0) = make_float2(acc[mt][nt][2], acc[mt][nt][3]);
        }
    }
}

// ---------------- conversion kernels ----------------
__global__ void __launch_bounds__(256) f32_to_f16_vec(
    const float* __restrict__ src, __half* __restrict__ dst)
{
    long i = (long)blockIdx.x * 256 + threadIdx.x;
    float4 v = ((const float4*)src)[i];
    ((__half2*)dst)[2 * i]     = __floats2half2_rn(v.x, v.y);
    ((__half2*)dst)[2 * i + 1] = __floats2half2_rn(v.z, v.w);
}

// dst[C][R] (half) = src[R][C]^T (f32)  -- used for W^T only
__global__ void __launch_bounds__(256) transpose_f16(
    const float* __restrict__ src, __half* __restrict__ dst, int R, int C)
{
    __shared__ float t[32][33];
    int c0 = blockIdx.x * 32, r0 = blockIdx.y * 32;
    int x = threadIdx.x, y = threadIdx.y;
    #pragma unroll
    for (int i = 0; i < 32; i += 8)
        t[y + i][x] = src[(long)(r0 + y + i) * C + c0 + x];
    __syncthreads();
    #pragma unroll
    for (int i = 0; i < 32; i += 8)
        dst[(long)(c0 + y + i) * R + r0 + x] = __float2half(t[x][y + i]);
}

// ---------------- split-K reduction for qW (writes half) ----------------
__global__ void __launch_bounds__(256) reduce_qw(
    const float* __restrict__ part, __half* __restrict__ qW_h)
{
    int i = (blockIdx.x * 256 + threadIdx.x) * 4;
    float4 s = make_float4(0.f, 0.f, 0.f, 0.f);
    #pragma unroll
    for (int z = 0; z < 8; z++) {
        float4 v = *(const float4*)(part + (long)z * (KQ * DIM) + i);
        s.x += v.x; s.y += v.y; s.z += v.z; s.w += v.w;
    }
    const float a = 1.0f / 32.0f;
    ((__half2*)qW_h)[i / 2]     = __floats2half2_rn(s.x * a, s.y * a);
    ((__half2*)qW_h)[i / 2 + 1] = __floats2half2_rn(s.z * a, s.w * a);
}

// ---------------- mask dtype detection ----------------
__global__ void detect_mask_kind(const unsigned char* __restrict__ m)
{
    if (threadIdx.x != 0 || blockIdx.x != 0) return;
    int cnt[4] = {0, 0, 0, 0};
    for (int i = 0; i < 4096; i++)
        if (m[i] != 0) cnt[i & 3]++;
    int kind;
    if (cnt[1] > 0)                    kind = 1;  // uint8 bool
    else if (cnt[2] > 0 || cnt[3] > 0) kind = 2;  // float32
    else                               kind = 0;  // int32 bool
    g_mask_kind = kind;
}

// ---------------- fused mask + softmax (fp32 att + half att) ----------------
__global__ void __launch_bounds__(256) mask_softmax(
    float* __restrict__ att, __half* __restrict__ att_h, const void* __restrict__ mask_raw)
{
    long row = blockIdx.x;
    float* p = att + row * (long)NK;
    __half* ph = att_h + row * (long)NK;
    int tid = threadIdx.x;
    int kind = g_mask_kind;

    const unsigned char* m8  = (const unsigned char*)mask_raw + row * (long)NK;
    const int*           m32 = (const int*)mask_raw           + row * (long)NK;
    const float*         mf  = (const float*)mask_raw         + row * (long)NK;

    float v[8];
    float lmax = -INFINITY;
    #pragma unroll
    for (int i = 0; i < 8; i++) {
        int idx = tid + i * 256;
        bool keep;
        if (kind == 0)      keep = (m32[idx] != 0);
        else if (kind == 1) keep = (m8[idx] != 0);
        else                keep = (mf[idx] != 0.0f);
        float s = keep ? p[idx] : -INFINITY;
        v[i] = s;
        lmax = fmaxf(lmax, s);
    }

    __shared__ float red[8];
    #pragma unroll
    for (int o = 16; o > 0; o >>= 1)
        lmax = fmaxf(lmax, __shfl_xor_sync(0xffffffffu, lmax, o));
    if ((tid & 31) == 0) red[tid >> 5] = lmax;
    __syncthreads();
    float rmax = fmaxf(fmaxf(fmaxf(red[0], red[1]), fmaxf(red[2], red[3])),
                       fmaxf(fmaxf(red[4], red[5]), fmaxf(red[6], red[7])));
    __syncthreads();

    float lsum = 0.f;
    #pragma unroll
    for (int i = 0; i < 8; i++) {
        float e = (v[i] == -INFINITY) ? 0.f : __expf(v[i] - rmax);
        v[i] = e;
        lsum += e;
    }
    #pragma unroll
    for (int o = 16; o > 0; o >>= 1)
        lsum += __shfl_xor_sync(0xffffffffu, lsum, o);
    if ((tid & 31) == 0) red[tid >> 5] = lsum;
    __syncthreads();
    float rsum = red[0] + red[1] + red[2] + red[3] + red[4] + red[5] + red[6] + red[7];
    float inv = (rsum > 0.f) ? (1.f / rsum) : 0.f;

    #pragma unroll
    for (int i = 0; i < 8; i++) {
        float r = v[i] * inv;
        int idx = tid + i * 256;
        p[idx] = r;
        ph[idx] = __float2half(r);
    }
}

// ---------------- launcher ----------------
extern "C" void kernel_launch(void* const* d_in, const int* in_sizes, int n_in,
                              void* d_out, int out_size)
{
    const float* query = (const float*)d_in[0];   // [KQ, DIM]
    const float* key   = (const float*)d_in[1];   // [BATCH, NK, DIM]
    const float* W     = (const float*)d_in[2];   // [DIM, DIM]
    const void*  mask  = d_in[3];                 // [BATCH, KQ, NK] bool

    float* out_ptr = (float*)d_out;
    const long outBKD = (long)BATCH * KQ * DIM;

    float *qW_part, *att_scratch;
    __half *qW_h, *query_h, *WT_h, *key_h, *att_h;
    cudaGetSymbolAddress((void**)&qW_part, g_qW_part);
    cudaGetSymbolAddress((void**)&qW_h, g_qW_h);
    cudaGetSymbolAddress((void**)&query_h, g_query_h);
    cudaGetSymbolAddress((void**)&WT_h, g_WT_h);
    cudaGetSymbolAddress((void**)&key_h, g_key_h);
    cudaGetSymbolAddress((void**)&att_h, g_att_h);
    cudaGetSymbolAddress((void**)&att_scratch, g_att_scratch);

    float* att_ptr = ((long)out_size > outBKD) ? (out_ptr + outBKD) : att_scratch;

    // 0) mask dtype detection
    detect_mask_kind<<<1, 1>>>((const unsigned char*)mask);

    // 1) conversions: query -> half, W -> W^T half, key -> half (native layout)
    f32_to_f16_vec<<<(KQ * DIM / 4) / 256, 256>>>(query, query_h);
    transpose_f16<<<dim3(DIM / 32, DIM / 32), dim3(32, 8)>>>(W, WT_h, DIM, DIM);
    f32_to_f16_vec<<<(int)(((long)BATCH * NK * DIM / 4) / 256), 256>>>(key, key_h);

    // 2) qW partials via split-K=8 (NT: A=query_h, B=WT_h), then reduce (/32) -> half
    gemm_nt_h<<<dim3(DIM / 128, KQ / 128, 8), 128>>>(
        query_h, WT_h, qW_part, 128, DIM, DIM, DIM,
        128L, 128L, (long)KQ * DIM);
    reduce_qw<<<KQ * DIM / (256 * 4), 256>>>(qW_part, qW_h);

    // 3) scores[b] = qW_h @ key_h[b]^T   (NT)
    gemm_nt_h<<<dim3(NK / 128, KQ / 128, BATCH), 128>>>(
        qW_h, key_h, att_ptr, DIM, DIM, DIM, NK,
        0L, (long)NK * DIM, (long)KQ * NK);

    // 4) mask + softmax in place (fp32 out) + half copy
    mask_softmax<<<BATCH * KQ, 256>>>(att_ptr, att_h, mask);

    // 5) out[b] = att_h[b] @ key_h[b]    (NN, B in native [n][d] layout)
    gemm_nn_h<<<dim3(DIM / 128, KQ / 128, BATCH), 128>>>(
        att_h, key_h, out_ptr, NK, NK, DIM, DIM,
        (long)KQ * NK, (long)NK * DIM, (long)KQ * DIM);
}

// round 11
// speedup vs baseline: 2.2606x; 1.0111x over previous
#include <cuda_runtime.h>
#include <cuda_fp16.h>
#include <math.h>
#include <stdint.h>

// Problem shapes (fixed by the reference)
#define BATCH 16
#define KQ    512
#define NK    2048
#define DIM   1024

// ---------------- scratch (no cudaMalloc allowed) ----------------
__device__ float  g_qW_part[8 * KQ * DIM];              // 16 MB split-K partials
__device__ __half g_qW_h[KQ * DIM];                     // 1 MB
__device__ __half g_query_h[KQ * DIM];                  // 1 MB
__device__ __half g_WT_h[DIM * DIM];                    // 2 MB  W^T [j][d]
__device__ __half g_key_h[(size_t)BATCH * NK * DIM];    // 64 MB key (half, native layout)
__device__ float  g_att_scratch[(size_t)BATCH * KQ * NK]; // 64 MB (if att not in d_out)
__device__ __half g_att_h[(size_t)BATCH * KQ * NK];     // 64 MB half att
__device__ int    g_mask_kind;                          // 0=int32, 1=uint8, 2=float32

// ---------------- helpers ----------------
__device__ __forceinline__ void cp16(uint32_t s, const void* g) {
    asm volatile("cp.async.cg.shared.global [%0], [%1], 16;" :: "r"(s), "l"(g));
}
__device__ __forceinline__ void cp_commit() {
    asm volatile("cp.async.commit_group;" ::: "memory");
}
__device__ __forceinline__ void cp_wait0() {
    asm volatile("cp.async.wait_group 0;" ::: "memory");
}
__device__ __forceinline__ void mma_f16(float* c, uint32_t a0, uint32_t a1,
                                        uint32_t a2, uint32_t a3,
                                        uint32_t b0, uint32_t b1) {
    asm volatile(
        "mma.sync.aligned.m16n8k16.row.col.f32.f16.f16.f32 "
        "{%0,%1,%2,%3}, {%4,%5,%6,%7}, {%8,%9}, {%0,%1,%2,%3};"
        : "+f"(c[0]), "+f"(c[1]), "+f"(c[2]), "+f"(c[3])
        : "r"(a0), "r"(a1), "r"(a2), "r"(a3), "r"(b0), "r"(b1));
}
__device__ __forceinline__ void ldsm4(uint32_t* r, uint32_t a) {
    asm volatile("ldmatrix.sync.aligned.m8n8.x4.shared.b16 {%0,%1,%2,%3}, [%4];"
        : "=r"(r[0]), "=r"(r[1]), "=r"(r[2]), "=r"(r[3]) : "r"(a));
}
__device__ __forceinline__ void ldsm4t(uint32_t* r, uint32_t a) {
    asm volatile("ldmatrix.sync.aligned.m8n8.x4.trans.shared.b16 {%0,%1,%2,%3}, [%4];"
        : "=r"(r[0]), "=r"(r[1]), "=r"(r[2]), "=r"(r[3]) : "r"(a));
}

#define HST 40    // A / NT-B tile row stride (halfs): 32 data + 8 pad
#define SBN 136   // NN-B tile row stride (halfs): 128 data + 8 pad

// =====================================================================
// fp16 mma GEMM, NT: C[M,N] = A[M,Kd] * B[N,Kd]^T  (both K-contig half)
// Block 128x128, 8 warps (2x4), warp tile 64x32, K-chunk 32 halfs,
// 2-stage cp.async double buffer, ldmatrix fragment loads.
// =====================================================================
__global__ void __launch_bounds__(256) gemm_nt_h(
    const __half* __restrict__ A, const __half* __restrict__ B, float* __restrict__ C,
    int Kd, int lda, int ldb, int ldc, long sA, long sB, long sC)
{
    __shared__ __half As[2][128 * HST];
    __shared__ __half Bs[2][128 * HST];

    const int tid  = threadIdx.x;
    const int wid  = tid >> 5;
    const int lane = tid & 31;
    const int wm   = wid & 1;        // 64-row half
    const int wn   = wid >> 1;       // 0..3  -> 32-col quarter
    const int grp  = lane >> 2;
    const int tig  = lane & 3;

    A += (long)blockIdx.z * sA + (long)blockIdx.y * 128 * lda;
    B += (long)blockIdx.z * sB + (long)blockIdx.x * 128 * ldb;
    C += (long)blockIdx.z * sC + (long)blockIdx.y * 128 * ldc + (long)blockIdx.x * 128;

    const int crow = tid >> 2;          // cp rows 0..63 (+64)
    const int cseg = (tid & 3) * 8;

    const uint32_t sa0 = (uint32_t)__cvta_generic_to_shared(&As[0][0]);
    const uint32_t sb0 = (uint32_t)__cvta_generic_to_shared(&Bs[0][0]);
    const uint32_t stgA = (uint32_t)(128 * HST * 2);

    const uint32_t offA = (uint32_t)(((wm * 64 + (lane & 15)) * HST + 8 * (lane >> 4)) * 2);
    const uint32_t offB = (uint32_t)(((wn * 32 + (lane & 7) + 8 * (lane >> 4)) * HST
                                      + 8 * ((lane >> 3) & 1)) * 2);

    float acc[4][4][4];
    #pragma unroll
    for (int i = 0; i < 4; i++)
        #pragma unroll
        for (int j = 0; j < 4; j++)
            #pragma unroll
            for (int t = 0; t < 4; t++) acc[i][j][t] = 0.f;

    const int NCH = Kd >> 5;

    // prologue: chunk 0 -> stage 0
    #pragma unroll
    for (int i = 0; i < 2; i++) {
        int row = crow + 64 * i;
        uint32_t d = (uint32_t)(row * HST + cseg) * 2;
        cp16(sa0 + d, A + (long)row * lda + cseg);
        cp16(sb0 + d, B + (long)row * ldb + cseg);
    }
    cp_commit();

    for (int kc = 0; kc < NCH; kc++) {
        cp_wait0();
        __syncthreads();

        if (kc + 1 < NCH) {
            const uint32_t so = ((kc + 1) & 1) * stgA;
            const __half* An = A + (long)(kc + 1) * 32;
            const __half* Bn = B + (long)(kc + 1) * 32;
            #pragma unroll
            for (int i = 0; i < 2; i++) {
                int row = crow + 64 * i;
                uint32_t d = (uint32_t)(row * HST + cseg) * 2;
                cp16(sa0 + so + d, An + (long)row * lda + cseg);
                cp16(sb0 + so + d, Bn + (long)row * ldb + cseg);
            }
            cp_commit();
        }

        const uint32_t so = (kc & 1) * stgA;
        #pragma unroll
        for (int g = 0; g < 2; g++) {
            uint32_t afr[4][4], bfr[2][4];
            #pragma unroll
            for (int mt = 0; mt < 4; mt++)
                ldsm4(afr[mt], sa0 + so + offA + (uint32_t)(mt * 16 * HST * 2 + g * 32));
            #pragma unroll
            for (int np = 0; np < 2; np++)
                ldsm4(bfr[np], sb0 + so + offB + (uint32_t)(np * 16 * HST * 2 + g * 32));
            #pragma unroll
            for (int mt = 0; mt < 4; mt++)
                #pragma unroll
                for (int np = 0; np < 2; np++) {
                    mma_f16(acc[mt][2 * np],     afr[mt][0], afr[mt][1], afr[mt][2], afr[mt][3],
                            bfr[np][0], bfr[np][1]);
                    mma_f16(acc[mt][2 * np + 1], afr[mt][0], afr[mt][1], afr[mt][2], afr[mt][3],
                            bfr[np][2], bfr[np][3]);
                }
        }
        __syncthreads();
    }

    #pragma unroll
    for (int mt = 0; mt < 4; mt++) {
        int r0 = wm * 64 + mt * 16 + grp;
        #pragma unroll
        for (int nt = 0; nt < 4; nt++) {
            int c0 = wn * 32 + nt * 8 + 2 * tig;
            *(float2*)(C + (long)r0 * ldc + c0)       = make_float2(acc[mt][nt][0], acc[mt][nt][1]);
            *(float2*)(C + (long)(r0 + 8) * ldc + c0) = make_float2(acc[mt][nt][2], acc[mt][nt][3]);
        }
    }
}

// =====================================================================
// fp16 mma GEMM, NN: C[M,N] = A[M,Kd] * B[Kd,N]  (B row-major half)
// Block 128x128, 8 warps (2x4), warp tile 64x32, B fragments via ldmatrix.trans.
// =====================================================================
__global__ void __launch_bounds__(256) gemm_nn_h(
    const __half* __restrict__ A, const __half* __restrict__ B, float* __restrict__ C,
    int Kd, int lda, int ldb, int ldc, long sA, long sB, long sC)
{
    __shared__ __half As[2][128 * HST];
    __shared__ __half Bs[2][32 * SBN];

    const int tid  = threadIdx.x;
    const int wid  = tid >> 5;
    const int lane = tid & 31;
    const int wm   = wid & 1;
    const int wn   = wid >> 1;       // 0..3
    const int grp  = lane >> 2;
    const int tig  = lane & 3;

    A += (long)blockIdx.z * sA + (long)blockIdx.y * 128 * lda;
    B += (long)blockIdx.z * sB + (long)blockIdx.x * 128;
    C += (long)blockIdx.z * sC + (long)blockIdx.y * 128 * ldc + (long)blockIdx.x * 128;

    const int crow = tid >> 2;          // A cp rows 0..63 (+64)
    const int cseg = (tid & 3) * 8;
    const int brow = tid >> 4;          // B cp rows 0..15 (+16)
    const int bseg = (tid & 15) * 8;

    const uint32_t sa0 = (uint32_t)__cvta_generic_to_shared(&As[0][0]);
    const uint32_t sb0 = (uint32_t)__cvta_generic_to_shared(&Bs[0][0]);
    const uint32_t stgA = (uint32_t)(128 * HST * 2);
    const uint32_t stgB = (uint32_t)(32 * SBN * 2);

    const uint32_t offA = (uint32_t)(((wm * 64 + (lane & 15)) * HST + 8 * (lane >> 4)) * 2);
    const uint32_t offB = (uint32_t)((((lane & 7) + 8 * ((lane >> 3) & 1)) * SBN
                                      + wn * 32 + 8 * (lane >> 4)) * 2);

    float acc[4][4][4];
    #pragma unroll
    for (int i = 0; i < 4; i++)
        #pragma unroll
        for (int j = 0; j < 4; j++)
            #pragma unroll
            for (int t = 0; t < 4; t++) acc[i][j][t] = 0.f;

    const int NCH = Kd >> 5;

    #pragma unroll
    for (int i = 0; i < 2; i++) {
        int arow = crow + 64 * i;
        cp16(sa0 + (uint32_t)(arow * HST + cseg) * 2, A + (long)arow * lda + cseg);
        int kr = brow + 16 * i;
        cp16(sb0 + (uint32_t)(kr * SBN + bseg) * 2, B + (long)kr * ldb + bseg);
    }
    cp_commit();

    for (int kc = 0; kc < NCH; kc++) {
        cp_wait0();
        __syncthreads();

        if (kc + 1 < NCH) {
            const uint32_t soA = ((kc + 1) & 1) * stgA;
            const uint32_t soB = ((kc + 1) & 1) * stgB;
            const __half* An = A + (long)(kc + 1) * 32;
            const __half* Bn = B + (long)(kc + 1) * 32 * ldb;
            #pragma unroll
            for (int i = 0; i < 2; i++) {
                int arow = crow + 64 * i;
                cp16(sa0 + soA + (uint32_t)(arow * HST + cseg) * 2, An + (long)arow * lda + cseg);
                int kr = brow + 16 * i;
                cp16(sb0 + soB + (uint32_t)(kr * SBN + bseg) * 2, Bn + (long)kr * ldb + bseg);
            }
            cp_commit();
        }

        const uint32_t soA = (kc & 1) * stgA;
        const uint32_t soB = (kc & 1) * stgB;
        #pragma unroll
        for (int g = 0; g < 2; g++) {
            uint32_t afr[4][4], bfr[2][4];
            #pragma unroll
            for (int mt = 0; mt < 4; mt++)
                ldsm4(afr[mt], sa0 + soA + offA + (uint32_t)(mt * 16 * HST * 2 + g * 32));
            #pragma unroll
            for (int np = 0; np < 2; np++)
                ldsm4t(bfr[np], sb0 + soB + offB + (uint32_t)(np * 32 + g * 16 * SBN * 2));
            #pragma unroll
            for (int mt = 0; mt < 4; mt++)
                #pragma unroll
                for (int np = 0; np < 2; np++) {
                    mma_f16(acc[mt][2 * np],     afr[mt][0], afr[mt][1], afr[mt][2], afr[mt][3],
                            bfr[np][0], bfr[np][1]);
                    mma_f16(acc[mt][2 * np + 1], afr[mt][0], afr[mt][1], afr[mt][2], afr[mt][3],
                            bfr[np][2], bfr[np][3]);
                }
        }
        __syncthreads();
    }

    #pragma unroll
    for (int mt = 0; mt < 4; mt++) {
        int r0 = wm * 64 + mt * 16 + grp;
        #pragma unroll
        for (int nt = 0; nt < 4; nt++) {
            int c0 = wn * 32 + nt * 8 + 2 * tig;
            *(float2*)(C + (long)r0 * ldc + c0)       = make_float2(acc[mt][nt][0], acc[mt][nt][1]);
            *(float2*)(C + (long)(r0 + 8) * ldc + c0) = make_float2(acc[mt][nt][2], acc[mt][nt][3]);
        }
    }
}

// ---------------- conversion kernels ----------------
__global__ void __launch_bounds__(256) f32_to_f16_vec(
    const float* __restrict__ src, __half* __restrict__ dst)
{
    long i = (long)blockIdx.x * 256 + threadIdx.x;
    float4 v = ((const float4*)src)[i];
    ((__half2*)dst)[2 * i]     = __floats2half2_rn(v.x, v.y);
    ((__half2*)dst)[2 * i + 1] = __floats2half2_rn(v.z, v.w);
}

// dst[C][R] (half) = src[R][C]^T (f32)  -- used for W^T only
__global__ void __launch_bounds__(256) transpose_f16(
    const float* __restrict__ src, __half* __restrict__ dst, int R, int C)
{
    __shared__ float t[32][33];
    int c0 = blockIdx.x * 32, r0 = blockIdx.y * 32;
    int x = threadIdx.x, y = threadIdx.y;
    #pragma unroll
    for (int i = 0; i < 32; i += 8)
        t[y + i][x] = src[(long)(r0 + y + i) * C + c0 + x];
    __syncthreads();
    #pragma unroll
    for (int i = 0; i < 32; i += 8)
        dst[(long)(c0 + y + i) * R + r0 + x] = __float2half(t[x][y + i]);
}

// ---------------- split-K reduction for qW (writes half) ----------------
__global__ void __launch_bounds__(256) reduce_qw(
    const float* __restrict__ part, __half* __restrict__ qW_h)
{
    int i = (blockIdx.x * 256 + threadIdx.x) * 4;
    float4 s = make_float4(0.f, 0.f, 0.f, 0.f);
    #pragma unroll
    for (int z = 0; z < 8; z++) {
        float4 v = *(const float4*)(part + (long)z * (KQ * DIM) + i);
        s.x += v.x; s.y += v.y; s.z += v.z; s.w += v.w;
    }
    const float a = 1.0f / 32.0f;
    ((__half2*)qW_h)[i / 2]     = __floats2half2_rn(s.x * a, s.y * a);
    ((__half2*)qW_h)[i / 2 + 1] = __floats2half2_rn(s.z * a, s.w * a);
}

// ---------------- mask dtype detection ----------------
__global__ void detect_mask_kind(const unsigned char* __restrict__ m)
{
    if (threadIdx.x != 0 || blockIdx.x != 0) return;
    int cnt[4] = {0, 0, 0, 0};
    for (int i = 0; i < 4096; i++)
        if (m[i] != 0) cnt[i & 3]++;
    int kind;
    if (cnt[1] > 0)                    kind = 1;  // uint8 bool
    else if (cnt[2] > 0 || cnt[3] > 0) kind = 2;  // float32
    else                               kind = 0;  // int32 bool
    g_mask_kind = kind;
}

// ---------------- fused mask + softmax (fp32 att + half att) ----------------
__global__ void __launch_bounds__(256) mask_softmax(
    float* __restrict__ att, __half* __restrict__ att_h, const void* __restrict__ mask_raw)
{
    long row = blockIdx.x;
    float* p = att + row * (long)NK;
    __half* ph = att_h + row * (long)NK;
    int tid = threadIdx.x;
    int kind = g_mask_kind;

    const unsigned char* m8  = (const unsigned char*)mask_raw + row * (long)NK;
    const int*           m32 = (const int*)mask_raw           + row * (long)NK;
    const float*         mf  = (const float*)mask_raw         + row * (long)NK;

    float v[8];
    float lmax = -INFINITY;
    #pragma unroll
    for (int i = 0; i < 8; i++) {
        int idx = tid + i * 256;
        bool keep;
        if (kind == 0)      keep = (m32[idx] != 0);
        else if (kind == 1) keep = (m8[idx] != 0);
        else                keep = (mf[idx] != 0.0f);
        float s = keep ? p[idx] : -INFINITY;
        v[i] = s;
        lmax = fmaxf(lmax, s);
    }

    __shared__ float red[8];
    #pragma unroll
    for (int o = 16; o > 0; o >>= 1)
        lmax = fmaxf(lmax, __shfl_xor_sync(0xffffffffu, lmax, o));
    if ((tid & 31) == 0) red[tid >> 5] = lmax;
    __syncthreads();
    float rmax = fmaxf(fmaxf(fmaxf(red[0], red[1]), fmaxf(red[2], red[3])),
                       fmaxf(fmaxf(red[4], red[5]), fmaxf(red[6], red[7])));
    __syncthreads();

    float lsum = 0.f;
    #pragma unroll
    for (int i = 0; i < 8; i++) {
        float e = (v[i] == -INFINITY) ? 0.f : __expf(v[i] - rmax);
        v[i] = e;
        lsum += e;
    }
    #pragma unroll
    for (int o = 16; o > 0; o >>= 1)
        lsum += __shfl_xor_sync(0xffffffffu, lsum, o);
    if ((tid & 31) == 0) red[tid >> 5] = lsum;
    __syncthreads();
    float rsum = red[0] + red[1] + red[2] + red[3] + red[4] + red[5] + red[6] + red[7];
    float inv = (rsum > 0.f) ? (1.f / rsum) : 0.f;

    #pragma unroll
    for (int i = 0; i < 8; i++) {
        float r = v[i] * inv;
        int idx = tid + i * 256;
        p[idx] = r;
        ph[idx] = __float2half(r);
    }
}

// ---------------- launcher ----------------
extern "C" void kernel_launch(void* const* d_in, const int* in_sizes, int n_in,
                              void* d_out, int out_size)
{
    const float* query = (const float*)d_in[0];   // [KQ, DIM]
    const float* key   = (const float*)d_in[1];   // [BATCH, NK, DIM]
    const float* W     = (const float*)d_in[2];   // [DIM, DIM]
    const void*  mask  = d_in[3];                 // [BATCH, KQ, NK] bool

    float* out_ptr = (float*)d_out;
    const long outBKD = (long)BATCH * KQ * DIM;

    float *qW_part, *att_scratch;
    __half *qW_h, *query_h, *WT_h, *key_h, *att_h;
    cudaGetSymbolAddress((void**)&qW_part, g_qW_part);
    cudaGetSymbolAddress((void**)&qW_h, g_qW_h);
    cudaGetSymbolAddress((void**)&query_h, g_query_h);
    cudaGetSymbolAddress((void**)&WT_h, g_WT_h);
    cudaGetSymbolAddress((void**)&key_h, g_key_h);
    cudaGetSymbolAddress((void**)&att_h, g_att_h);
    cudaGetSymbolAddress((void**)&att_scratch, g_att_scratch);

    float* att_ptr = ((long)out_size > outBKD) ? (out_ptr + outBKD) : att_scratch;

    // 0) mask dtype detection
    detect_mask_kind<<<1, 1>>>((const unsigned char*)mask);

    // 1) conversions: query -> half, W -> W^T half, key -> half (native layout)
    f32_to_f16_vec<<<(KQ * DIM / 4) / 256, 256>>>(query, query_h);
    transpose_f16<<<dim3(DIM / 32, DIM / 32), dim3(32, 8)>>>(W, WT_h, DIM, DIM);
    f32_to_f16_vec<<<(int)(((long)BATCH * NK * DIM / 4) / 256), 256>>>(key, key_h);

    // 2) qW partials via split-K=8 (NT: A=query_h, B=WT_h), then reduce (/32) -> half
    gemm_nt_h<<<dim3(DIM / 128, KQ / 128, 8), 256>>>(
        query_h, WT_h, qW_part, 128, DIM, DIM, DIM,
        128L, 128L, (long)KQ * DIM);
    reduce_qw<<<KQ * DIM / (256 * 4), 256>>>(qW_part, qW_h);

    // 3) scores[b] = qW_h @ key_h[b]^T   (NT)
    gemm_nt_h<<<dim3(NK / 128, KQ / 128, BATCH), 256>>>(
        qW_h, key_h, att_ptr, DIM, DIM, DIM, NK,
        0L, (long)NK * DIM, (long)KQ * NK);

    // 4) mask + softmax in place (fp32 out) + half copy
    mask_softmax<<<BATCH * KQ, 256>>>(att_ptr, att_h, mask);

    // 5) out[b] = att_h[b] @ key_h[b]    (NN, B in native [n][d] layout)
    gemm_nn_h<<<dim3(DIM / 128, KQ / 128, BATCH), 256>>>(
        att_h, key_h, out_ptr, NK, NK, DIM, DIM,
        (long)KQ * NK, (long)NK * DIM, (long)KQ * DIM);
}